// round 9
// baseline (speedup 1.0000x reference)
#include <cuda_runtime.h>
#include <cuda_fp16.h>
#include <math.h>
#include <stdint.h>

#define DIN   128
#define N_MAX 100000
#define E_MAX 1600000
#define T_MAX (E_MAX + N_MAX)

// ---------------------------------------------------------------------------
// persistent scratch (no allocations allowed)
// ---------------------------------------------------------------------------
__device__ __half g_h  [(size_t)N_MAX * 128];   // gemm output h (fp16 gather path)
__device__ __half g_xh [(size_t)N_MAX * 128];   // layer output (fp16, next gemm input)
__device__ float  g_bufB[(size_t)N_MAX * 128];  // layer-3 output (fp32, for mean)
__device__ float  g_ssrc[N_MAX];
__device__ float  g_sdst[N_MAX];
__device__ __half g_wt1[128 * 128];
__device__ __half g_wt2[128 * 128];
__device__ __half g_wt3[64 * 128];
__device__ float  g_mpart[1024 * 64];

__device__ int g_cnt   [N_MAX];
__device__ int g_tmp   [N_MAX];
__device__ int g_rowptr[N_MAX + 1];
__device__ int g_cursor[N_MAX];
__device__ int g_bsum  [256];
__device__ int g_csrc  [T_MAX];

static inline int ceil_div(int a, int b) { return (a + b - 1) / b; }

// ---------------------------------------------------------------------------
// mma / ldmatrix helpers
// ---------------------------------------------------------------------------
__device__ __forceinline__ void mma_f16(float c[4], uint32_t a0, uint32_t a1,
                                        uint32_t a2, uint32_t a3,
                                        uint32_t b0, uint32_t b1) {
    asm volatile(
        "mma.sync.aligned.m16n8k16.row.col.f32.f16.f16.f32 "
        "{%0,%1,%2,%3}, {%4,%5,%6,%7}, {%8,%9}, {%0,%1,%2,%3};"
        : "+f"(c[0]), "+f"(c[1]), "+f"(c[2]), "+f"(c[3])
        : "r"(a0), "r"(a1), "r"(a2), "r"(a3), "r"(b0), "r"(b1));
}

__device__ __forceinline__ void ldsm_x4(uint32_t& r0, uint32_t& r1,
                                        uint32_t& r2, uint32_t& r3,
                                        uint32_t addr) {
    asm volatile("ldmatrix.sync.aligned.m8n8.x4.shared.b16 {%0,%1,%2,%3}, [%4];"
                 : "=r"(r0), "=r"(r1), "=r"(r2), "=r"(r3) : "r"(addr));
}

__device__ __forceinline__ uint32_t smem_u32(const void* p) {
    uint32_t a;
    asm("{ .reg .u64 t; cvta.to.shared.u64 t, %1; cvt.u32.u64 %0, t; }"
        : "=r"(a) : "l"(p));
    return a;
}

// ---------------------------------------------------------------------------
// one-shot W transposes for all 3 layers: Wt[n][k] (fp16) = W[k][n] (fp32)
// ---------------------------------------------------------------------------
__global__ void wt_all_kernel(const float* __restrict__ W1,
                              const float* __restrict__ W2,
                              const float* __restrict__ W3,
                              __half* __restrict__ Wt1,
                              __half* __restrict__ Wt2,
                              __half* __restrict__ Wt3) {
    int i = blockIdx.x * 256 + threadIdx.x;
    if (i < 128 * 128) {
        int n = i >> 7, k = i & 127;
        Wt1[i] = __float2half(W1[k * 128 + n]);
    } else if (i < 2 * 128 * 128) {
        int j = i - 128 * 128;
        int n = j >> 7, k = j & 127;
        Wt2[j] = __float2half(W2[k * 128 + n]);
    } else if (i < 2 * 128 * 128 + 64 * 128) {
        int l = i - 2 * 128 * 128;
        int n = l >> 7, k = l & 127;
        Wt3[l] = __float2half(W3[k * 64 + n]);
    }
}

// ---------------------------------------------------------------------------
// GEMM (tensor core, fp16 in / fp32 acc, ldmatrix fragments) + fused scores
// (unchanged from round 8 — verified win)
// ---------------------------------------------------------------------------
template<int DOUT, typename XT>
__global__ __launch_bounds__(256)
void gemm_f16_kernel(const XT* __restrict__ X, const __half* __restrict__ Wt,
                     const float* __restrict__ avs, const float* __restrict__ avd,
                     __half* __restrict__ H,
                     float* __restrict__ s_src, float* __restrict__ s_dst, int N)
{
    extern __shared__ __half hsmem[];
    constexpr int AP = 136;                    // padded row stride (halves)
    __half* As  = hsmem;                       // [128][AP]
    __half* Bst = hsmem + 128 * AP;            // [DOUT][AP]

    const int tid  = threadIdx.x;
    const int lane = tid & 31;
    const int w    = tid >> 5;
    const int row_base = blockIdx.x * 128;

    // ---- stage A (128 x 128) ----
    if (sizeof(XT) == 4) {                     // fp32 input (layer 1)
        const float* Xf = (const float*)X;
        #pragma unroll
        for (int i = tid; i < 128 * 32; i += 256) {
            int r = i >> 5, c = (i & 31) * 4;
            float4 v = make_float4(0.f, 0.f, 0.f, 0.f);
            if (row_base + r < N) v = *(const float4*)(Xf + (size_t)(row_base + r) * 128 + c);
            __half2 h0 = __floats2half2_rn(v.x, v.y);
            __half2 h1 = __floats2half2_rn(v.z, v.w);
            uint2 u; u.x = *(uint32_t*)&h0; u.y = *(uint32_t*)&h1;
            *(uint2*)(As + r * AP + c) = u;
        }
    } else {                                   // fp16 input (layers 2-3)
        const __half* Xh = (const __half*)X;
        #pragma unroll
        for (int i = tid; i < 128 * 16; i += 256) {
            int r = i >> 4, c = (i & 15) * 8;
            uint4 v = make_uint4(0u, 0u, 0u, 0u);
            if (row_base + r < N) v = *(const uint4*)(Xh + (size_t)(row_base + r) * 128 + c);
            *(uint4*)(As + r * AP + c) = v;
        }
    }
    // ---- stage B: vector copy of pre-transposed Wt (conflict-free) ----
    #pragma unroll
    for (int i = tid; i < DOUT * 16; i += 256) {
        int n = i >> 4, kc = (i & 15) * 8;
        uint4 v = *(const uint4*)(Wt + n * 128 + kc);
        *(uint4*)(Bst + n * AP + kc) = v;
    }
    __syncthreads();

    constexpr int NT = DOUT / 8;
    float acc[NT][4];
    #pragma unroll
    for (int nt = 0; nt < NT; nt++)
        #pragma unroll
        for (int j = 0; j < 4; j++) acc[nt][j] = 0.f;

    const int g = lane >> 2;       // 0..7
    const int q = lane & 3;        // 0..3

    const uint32_t a_base = smem_u32(As) +
        (uint32_t)(((w * 16 + (lane & 15)) * AP + (lane >> 4) * 8) * 2);
    const uint32_t b_base = smem_u32(Bst) +
        (uint32_t)(((((lane & 7) + ((lane >> 4) * 8)) * AP) + ((lane >> 3) & 1) * 8) * 2);

    #pragma unroll
    for (int k0 = 0; k0 < 128; k0 += 16) {
        uint32_t a0, a1, a2, a3;
        ldsm_x4(a0, a1, a2, a3, a_base + k0 * 2);
        #pragma unroll
        for (int nt2 = 0; nt2 < NT / 2; nt2++) {
            uint32_t b0, b1, b2, b3;
            ldsm_x4(b0, b1, b2, b3, b_base + (uint32_t)((nt2 * 16 * AP + k0) * 2));
            mma_f16(acc[2 * nt2],     a0, a1, a2, a3, b0, b1);
            mma_f16(acc[2 * nt2 + 1], a0, a1, a2, a3, b2, b3);
        }
    }

    const int r0 = row_base + w * 16 + g;
    const int r1 = r0 + 8;

    float s1r0 = 0.f, s2r0 = 0.f, s1r1 = 0.f, s2r1 = 0.f;
    #pragma unroll
    for (int nt = 0; nt < NT; nt++) {
        int col = nt * 8 + 2 * q;
        float as0 = __ldg(&avs[col]), as1 = __ldg(&avs[col + 1]);
        float ad0 = __ldg(&avd[col]), ad1 = __ldg(&avd[col + 1]);
        s1r0 += acc[nt][0] * as0 + acc[nt][1] * as1;
        s2r0 += acc[nt][0] * ad0 + acc[nt][1] * ad1;
        s1r1 += acc[nt][2] * as0 + acc[nt][3] * as1;
        s2r1 += acc[nt][2] * ad0 + acc[nt][3] * ad1;
        if (r0 < N) *(__half2*)(H + (size_t)r0 * DOUT + col) =
            __floats2half2_rn(acc[nt][0], acc[nt][1]);
        if (r1 < N) *(__half2*)(H + (size_t)r1 * DOUT + col) =
            __floats2half2_rn(acc[nt][2], acc[nt][3]);
    }
    #pragma unroll
    for (int o = 1; o < 4; o <<= 1) {
        s1r0 += __shfl_xor_sync(0xffffffffu, s1r0, o);
        s2r0 += __shfl_xor_sync(0xffffffffu, s2r0, o);
        s1r1 += __shfl_xor_sync(0xffffffffu, s1r1, o);
        s2r1 += __shfl_xor_sync(0xffffffffu, s2r1, o);
    }
    if (q == 0) {
        if (r0 < N) { s_src[r0] = s1r0; s_dst[r0] = s2r0; }
        if (r1 < N) { s_src[r1] = s1r1; s_dst[r1] = s2r1; }
    }
}

// ---------------------------------------------------------------------------
// CSR build (per-dst): zero, histogram, scan1, fused scan2+3, fill
// ---------------------------------------------------------------------------
__global__ void zero_cnt_kernel(int* __restrict__ cnt, int N) {
    int i = blockIdx.x * blockDim.x + threadIdx.x;
    if (i < N) cnt[i] = 0;
}

__global__ void hist_kernel(const int* __restrict__ ei, int E, int N,
                            int* __restrict__ cnt) {
    int e = blockIdx.x * blockDim.x + threadIdx.x;
    int total = E + N;
    if (e >= total) return;
    int d = (e < E) ? ei[E + e] : (e - E);
    atomicAdd(&cnt[d], 1);
}

__global__ void scan1_kernel(const int* __restrict__ cnt, int N,
                             int* __restrict__ tmp, int* __restrict__ bsum) {
    __shared__ int sh[1024];
    int i = blockIdx.x * 1024 + threadIdx.x;
    int v = (i < N) ? cnt[i] : 0;
    sh[threadIdx.x] = v;
    __syncthreads();
    #pragma unroll
    for (int off = 1; off < 1024; off <<= 1) {
        int t = (threadIdx.x >= off) ? sh[threadIdx.x - off] : 0;
        __syncthreads();
        sh[threadIdx.x] += t;
        __syncthreads();
    }
    if (i < N) tmp[i] = sh[threadIdx.x];
    if (threadIdx.x == 1023) bsum[blockIdx.x] = sh[1023];
}

__global__ void scan23_kernel(const int* __restrict__ tmp,
                              const int* __restrict__ bsum,
                              const int* __restrict__ cnt,
                              int* __restrict__ rowptr,
                              int* __restrict__ cursor, int N, int nb) {
    __shared__ int sh[256];
    __shared__ int ex[256];
    int t = threadIdx.x;
    int v = (t < nb) ? bsum[t] : 0;
    sh[t] = v;
    __syncthreads();
    #pragma unroll
    for (int off = 1; off < 256; off <<= 1) {
        int u = (t >= off) ? sh[t - off] : 0;
        __syncthreads();
        sh[t] += u;
        __syncthreads();
    }
    ex[t] = sh[t] - v;   // exclusive block offsets
    __syncthreads();

    int i = blockIdx.x * blockDim.x + t;
    if (i < N) {
        int incl = tmp[i] + ex[i >> 10];
        rowptr[i + 1] = incl;
        cursor[i] = incl - cnt[i];
        if (i == 0) rowptr[0] = 0;
    }
}

__global__ void fill_kernel(const int* __restrict__ ei, int E, int N,
                            int* __restrict__ cursor, int* __restrict__ csrc) {
    int e = blockIdx.x * blockDim.x + threadIdx.x;
    int total = E + N;
    if (e >= total) return;
    int s, d;
    if (e < E) { s = ei[e]; d = ei[E + e]; } else { s = d = e - E; }
    int pos = atomicAdd(&cursor[d], 1);
    csrc[pos] = s;
}

// ---------------------------------------------------------------------------
// fused per-node aggregation; deferred denom reduce + 4-deep gather MLP
// ---------------------------------------------------------------------------
#define ECACHE 8

template<int DOUT, typename OutT>
__global__ __launch_bounds__(256)
void aggregate_kernel(const int* __restrict__ rowptr,
                      const int* __restrict__ csrc,
                      const float* __restrict__ s_src,
                      const float* __restrict__ s_dst,
                      const __half* __restrict__ H,
                      const float* __restrict__ bias,
                      OutT* __restrict__ out, int N)
{
    const int warp = (blockIdx.x * blockDim.x + threadIdx.x) >> 5;
    const int lane = threadIdx.x & 31;
    if (warp >= N) return;
    const int d   = warp;
    const int beg = rowptr[d];
    const int end = rowptr[d + 1];
    const int deg = end - beg;
    const float sd = s_dst[d];

    int   ss[ECACHE];
    float aa[ECACHE];

    // score pass: load, leaky-relu, exp, cache, per-lane denom (reduce deferred)
    float den = 0.f;
    int cnt = 0;
    for (int i = beg + lane; i < end; i += 32) {
        int s = __ldg(&csrc[i]);
        float v = __ldg(&s_src[s]) + sd;
        v = (v > 0.f) ? v : 0.2f * v;
        float a = __expf(v);
        if (cnt < ECACHE) { ss[cnt] = s; aa[cnt] = a; }
        cnt++;
        den += a;
    }

    // gather pass: EPAR edges in parallel, 4 loads in flight per lane
    constexpr int EPAR = (DOUT == 128) ? 2 : 4;    // edges per warp step
    constexpr int LPE  = 32 / EPAR;                // lanes per edge
    const int eoff = lane / LPE;                   // which edge in group
    const int fl   = lane % LPE;                   // feature chunk (8 halves)

    const int rounds = (deg + 31) >> 5;
    float4 acc0 = make_float4(0.f, 0.f, 0.f, 0.f);
    float4 acc1 = make_float4(0.f, 0.f, 0.f, 0.f);

    for (int j0 = 0; j0 < rounds; j0++) {
        int sv; float av;
        if (j0 < ECACHE) { sv = ss[j0]; av = aa[j0]; }
        else {
            int i = beg + j0 * 32 + lane;
            sv = 0; av = 0.f;
            if (i < end) {
                sv = __ldg(&csrc[i]);
                float v = __ldg(&s_src[sv]) + sd;
                v = (v > 0.f) ? v : 0.2f * v;
                av = __expf(v);
            }
        }
        const int tmax = min(32, deg - j0 * 32);
        for (int t = 0; t < tmax; t += 4 * EPAR) {
            uint4 u[4]; float ab[4]; int ok[4];
            #pragma unroll
            for (int b = 0; b < 4; b++) {
                int idx = t + b * EPAR + eoff;
                int   s = __shfl_sync(0xffffffffu, sv, idx & 31);
                ab[b]   = __shfl_sync(0xffffffffu, av, idx & 31);
                ok[b]   = (idx < tmax);
                if (ok[b]) u[b] = *(const uint4*)(H + (size_t)s * DOUT + fl * 8);
            }
            #pragma unroll
            for (int b = 0; b < 4; b++) {
                if (ok[b]) {
                    float a = ab[b];
                    float2 f0 = __half22float2(*(__half2*)&u[b].x);
                    float2 f1 = __half22float2(*(__half2*)&u[b].y);
                    float2 f2 = __half22float2(*(__half2*)&u[b].z);
                    float2 f3 = __half22float2(*(__half2*)&u[b].w);
                    acc0.x += f0.x * a; acc0.y += f0.y * a;
                    acc0.z += f1.x * a; acc0.w += f1.y * a;
                    acc1.x += f2.x * a; acc1.y += f2.y * a;
                    acc1.z += f3.x * a; acc1.w += f3.y * a;
                }
            }
        }
    }

    // deferred denom reduce
    #pragma unroll
    for (int o = 16; o > 0; o >>= 1)
        den += __shfl_xor_sync(0xffffffffu, den, o);

    // combine partial sums across edge groups
    #pragma unroll
    for (int o = LPE; o < 32; o <<= 1) {
        acc0.x += __shfl_xor_sync(0xffffffffu, acc0.x, o);
        acc0.y += __shfl_xor_sync(0xffffffffu, acc0.y, o);
        acc0.z += __shfl_xor_sync(0xffffffffu, acc0.z, o);
        acc0.w += __shfl_xor_sync(0xffffffffu, acc0.w, o);
        acc1.x += __shfl_xor_sync(0xffffffffu, acc1.x, o);
        acc1.y += __shfl_xor_sync(0xffffffffu, acc1.y, o);
        acc1.z += __shfl_xor_sync(0xffffffffu, acc1.z, o);
        acc1.w += __shfl_xor_sync(0xffffffffu, acc1.w, o);
    }
    if (eoff == 0) {
        float inv = 1.0f / den;
        float4 b0 = *(const float4*)(bias + fl * 8);
        float4 b1 = *(const float4*)(bias + fl * 8 + 4);
        float r0 = acc0.x * inv + b0.x, r1 = acc0.y * inv + b0.y;
        float r2 = acc0.z * inv + b0.z, r3 = acc0.w * inv + b0.w;
        float r4 = acc1.x * inv + b1.x, r5 = acc1.y * inv + b1.y;
        float r6 = acc1.z * inv + b1.z, r7 = acc1.w * inv + b1.w;
        if (sizeof(OutT) == 2) {
            __half2 p0 = __floats2half2_rn(r0, r1);
            __half2 p1 = __floats2half2_rn(r2, r3);
            __half2 p2 = __floats2half2_rn(r4, r5);
            __half2 p3 = __floats2half2_rn(r6, r7);
            uint4 u; u.x = *(uint32_t*)&p0; u.y = *(uint32_t*)&p1;
                    u.z = *(uint32_t*)&p2; u.w = *(uint32_t*)&p3;
            *(uint4*)((__half*)out + (size_t)d * DOUT + fl * 8) = u;
        } else {
            float* of = (float*)out;
            *(float4*)(of + (size_t)d * DOUT + fl * 8)     = make_float4(r0, r1, r2, r3);
            *(float4*)(of + (size_t)d * DOUT + fl * 8 + 4) = make_float4(r4, r5, r6, r7);
        }
    }
}

// ---------------------------------------------------------------------------
// two-stage mean over nodes of final [N, 64] features (no atomics, no zeroing)
// ---------------------------------------------------------------------------
__global__ void mean_part_kernel(const float* __restrict__ H,
                                 float* __restrict__ part, int N)
{
    int col   = threadIdx.x & 63;
    int rbase = blockIdx.x * 4 + (threadIdx.x >> 6);
    float acc = 0.f;
    for (int r = rbase; r < N; r += gridDim.x * 4)
        acc += H[(size_t)r * 64 + col];
    __shared__ float sh[256];
    sh[threadIdx.x] = acc;
    __syncthreads();
    if (threadIdx.x < 64) {
        part[blockIdx.x * 64 + threadIdx.x] =
            sh[threadIdx.x] + sh[threadIdx.x + 64] +
            sh[threadIdx.x + 128] + sh[threadIdx.x + 192];
    }
}

__global__ void mean_final_kernel(const float* __restrict__ part,
                                  float* __restrict__ out, int nparts, int N)
{
    int col = threadIdx.x & 63;
    int seg = threadIdx.x >> 6;           // 0..3
    float acc = 0.f;
    for (int r = seg; r < nparts; r += 4)
        acc += part[r * 64 + col];
    __shared__ float sh[256];
    sh[threadIdx.x] = acc;
    __syncthreads();
    if (threadIdx.x < 64) {
        float v = sh[threadIdx.x] + sh[threadIdx.x + 64] +
                  sh[threadIdx.x + 128] + sh[threadIdx.x + 192];
        out[threadIdx.x] = v * (1.0f / (float)N);
    }
}

// ---------------------------------------------------------------------------
// host driver
// ---------------------------------------------------------------------------
extern "C" void kernel_launch(void* const* d_in, const int* in_sizes, int n_in,
                              void* d_out, int out_size)
{
    const float* x   = (const float*)d_in[0];
    const int*   ei  = (const int*)  d_in[1];
    const float* W1  = (const float*)d_in[2];
    const float* as1 = (const float*)d_in[3];
    const float* ad1 = (const float*)d_in[4];
    const float* b1  = (const float*)d_in[5];
    const float* W2  = (const float*)d_in[6];
    const float* as2 = (const float*)d_in[7];
    const float* ad2 = (const float*)d_in[8];
    const float* b2  = (const float*)d_in[9];
    const float* W3  = (const float*)d_in[10];
    const float* as3 = (const float*)d_in[11];
    const float* ad3 = (const float*)d_in[12];
    const float* b3  = (const float*)d_in[13];

    const int N = in_sizes[0] / 128;
    const int E = in_sizes[1] / 2;
    const int T = E + N;
    const int NB = ceil_div(N, 1024);

    float *pB, *pS1, *pS2, *pMp;
    __half *pH, *pXh, *pWt1, *pWt2, *pWt3;
    int *pCnt, *pTmp, *pRow, *pCur, *pBsum, *pCsrc;
    cudaGetSymbolAddress((void**)&pH,    g_h);
    cudaGetSymbolAddress((void**)&pXh,   g_xh);
    cudaGetSymbolAddress((void**)&pB,    g_bufB);
    cudaGetSymbolAddress((void**)&pS1,   g_ssrc);
    cudaGetSymbolAddress((void**)&pS2,   g_sdst);
    cudaGetSymbolAddress((void**)&pWt1,  g_wt1);
    cudaGetSymbolAddress((void**)&pWt2,  g_wt2);
    cudaGetSymbolAddress((void**)&pWt3,  g_wt3);
    cudaGetSymbolAddress((void**)&pMp,   g_mpart);
    cudaGetSymbolAddress((void**)&pCnt,  g_cnt);
    cudaGetSymbolAddress((void**)&pTmp,  g_tmp);
    cudaGetSymbolAddress((void**)&pRow,  g_rowptr);
    cudaGetSymbolAddress((void**)&pCur,  g_cursor);
    cudaGetSymbolAddress((void**)&pBsum, g_bsum);
    cudaGetSymbolAddress((void**)&pCsrc, g_csrc);

    // dynamic smem for fp16 GEMMs
    const int smem128 = (128 * 136 + 128 * 136) * 2;   // 69632
    const int smem64  = (128 * 136 + 64 * 136) * 2;    // 52224
    cudaFuncSetAttribute(gemm_f16_kernel<128, float>,
                         cudaFuncAttributeMaxDynamicSharedMemorySize, smem128);
    cudaFuncSetAttribute(gemm_f16_kernel<128, __half>,
                         cudaFuncAttributeMaxDynamicSharedMemorySize, smem128);
    cudaFuncSetAttribute(gemm_f16_kernel<64, __half>,
                         cudaFuncAttributeMaxDynamicSharedMemorySize, smem64);

    // ---------------- CSR build + layer-1 GEMM interleaved ----------------
    // (gemm1 kept at launch index 3 so the fixed ncu slot profiles it)
    zero_cnt_kernel<<<ceil_div(N, 256), 256>>>(pCnt, N);                          // 0
    hist_kernel<<<ceil_div(T, 256), 256>>>(ei, E, N, pCnt);                       // 1
    wt_all_kernel<<<160, 256>>>(W1, W2, W3, pWt1, pWt2, pWt3);                    // 2
    gemm_f16_kernel<128, float><<<ceil_div(N, 128), 256, smem128>>>(              // 3
        x, pWt1, as1, ad1, pH, pS1, pS2, N);
    scan1_kernel<<<NB, 1024>>>(pCnt, N, pTmp, pBsum);                             // 4
    scan23_kernel<<<ceil_div(N, 256), 256>>>(pTmp, pBsum, pCnt, pRow, pCur, N, NB); // 5
    fill_kernel<<<ceil_div(T, 256), 256>>>(ei, E, N, pCur, pCsrc);                // 6

    // ---------------- layer 1 aggregate -> pXh (fp16) ----------------
    aggregate_kernel<128, __half><<<ceil_div(N, 8), 256>>>(pRow, pCsrc, pS1, pS2, pH, b1, pXh, N);

    // ---------------- layer 2: pXh -> pXh (dout=128) ----------------
    gemm_f16_kernel<128, __half><<<ceil_div(N, 128), 256, smem128>>>(
        pXh, pWt2, as2, ad2, pH, pS1, pS2, N);
    aggregate_kernel<128, __half><<<ceil_div(N, 8), 256>>>(pRow, pCsrc, pS1, pS2, pH, b2, pXh, N);

    // ---------------- layer 3: pXh -> pB (dout=64, fp32 out) ----------------
    gemm_f16_kernel<64, __half><<<ceil_div(N, 128), 256, smem64>>>(
        pXh, pWt3, as3, ad3, pH, pS1, pS2, N);
    aggregate_kernel<64, float><<<ceil_div(N, 8), 256>>>(pRow, pCsrc, pS1, pS2, pH, b3, pB, N);

    // ---------------- global mean -> d_out [64] ----------------
    mean_part_kernel<<<1024, 256>>>(pB, pMp, N);
    mean_final_kernel<<<1, 256>>>(pMp, (float*)d_out, 1024, N);
}

// round 10
// speedup vs baseline: 1.0474x; 1.0474x over previous
#include <cuda_runtime.h>
#include <cuda_fp16.h>
#include <math.h>
#include <stdint.h>

#define DIN   128
#define N_MAX 100000
#define E_MAX 1600000
#define T_MAX (E_MAX + N_MAX)

// ---------------------------------------------------------------------------
// persistent scratch (no allocations allowed)
// ---------------------------------------------------------------------------
__device__ __half g_h  [(size_t)N_MAX * 128];   // gemm output h (fp16 gather path)
__device__ __half g_xh [(size_t)N_MAX * 128];   // layer output (fp16)
__device__ float  g_ssrc[N_MAX];
__device__ float  g_sdst[N_MAX];
__device__ __half g_wt1[128 * 128];
__device__ __half g_wt2[128 * 128];
__device__ __half g_wt3[64 * 128];
__device__ float  g_mpart[1024 * 64];

__device__ int g_cnt   [N_MAX];
__device__ int g_tmp   [N_MAX];
__device__ int g_rowptr[N_MAX + 1];
__device__ int g_cursor[N_MAX];
__device__ int g_bsum  [256];
__device__ int g_csrc  [T_MAX];

static inline int ceil_div(int a, int b) { return (a + b - 1) / b; }

// ---------------------------------------------------------------------------
// mma / ldmatrix helpers
// ---------------------------------------------------------------------------
__device__ __forceinline__ void mma_f16(float c[4], uint32_t a0, uint32_t a1,
                                        uint32_t a2, uint32_t a3,
                                        uint32_t b0, uint32_t b1) {
    asm volatile(
        "mma.sync.aligned.m16n8k16.row.col.f32.f16.f16.f32 "
        "{%0,%1,%2,%3}, {%4,%5,%6,%7}, {%8,%9}, {%0,%1,%2,%3};"
        : "+f"(c[0]), "+f"(c[1]), "+f"(c[2]), "+f"(c[3])
        : "r"(a0), "r"(a1), "r"(a2), "r"(a3), "r"(b0), "r"(b1));
}

__device__ __forceinline__ void ldsm_x4(uint32_t& r0, uint32_t& r1,
                                        uint32_t& r2, uint32_t& r3,
                                        uint32_t addr) {
    asm volatile("ldmatrix.sync.aligned.m8n8.x4.shared.b16 {%0,%1,%2,%3}, [%4];"
                 : "=r"(r0), "=r"(r1), "=r"(r2), "=r"(r3) : "r"(addr));
}

__device__ __forceinline__ uint32_t smem_u32(const void* p) {
    uint32_t a;
    asm("{ .reg .u64 t; cvta.to.shared.u64 t, %1; cvt.u32.u64 %0, t; }"
        : "=r"(a) : "l"(p));
    return a;
}

// ---------------------------------------------------------------------------
// fused: zero cnt[] + W transposes for all 3 layers (Wt[n][k] fp16 = W[k][n])
// ---------------------------------------------------------------------------
__global__ void init_wt_kernel(const float* __restrict__ W1,
                               const float* __restrict__ W2,
                               const float* __restrict__ W3,
                               __half* __restrict__ Wt1,
                               __half* __restrict__ Wt2,
                               __half* __restrict__ Wt3,
                               int* __restrict__ cnt, int N) {
    int i = blockIdx.x * 256 + threadIdx.x;
    if (i < N) cnt[i] = 0;
    if (i < 128 * 128) {
        int n = i >> 7, k = i & 127;
        Wt1[i] = __float2half(W1[k * 128 + n]);
    } else if (i < 2 * 128 * 128) {
        int j = i - 128 * 128;
        int n = j >> 7, k = j & 127;
        Wt2[j] = __float2half(W2[k * 128 + n]);
    } else if (i < 2 * 128 * 128 + 64 * 128) {
        int l = i - 2 * 128 * 128;
        int n = l >> 7, k = l & 127;
        Wt3[l] = __float2half(W3[k * 64 + n]);
    }
}

// ---------------------------------------------------------------------------
// GEMM (tensor core, fp16 in / fp32 acc, ldmatrix fragments) + fused scores
// (frozen since round 8 — verified win)
// ---------------------------------------------------------------------------
template<int DOUT, typename XT>
__global__ __launch_bounds__(256)
void gemm_f16_kernel(const XT* __restrict__ X, const __half* __restrict__ Wt,
                     const float* __restrict__ avs, const float* __restrict__ avd,
                     __half* __restrict__ H,
                     float* __restrict__ s_src, float* __restrict__ s_dst, int N)
{
    extern __shared__ __half hsmem[];
    constexpr int AP = 136;                    // padded row stride (halves)
    __half* As  = hsmem;                       // [128][AP]
    __half* Bst = hsmem + 128 * AP;            // [DOUT][AP]

    const int tid  = threadIdx.x;
    const int lane = tid & 31;
    const int w    = tid >> 5;
    const int row_base = blockIdx.x * 128;

    // ---- stage A (128 x 128) ----
    if (sizeof(XT) == 4) {                     // fp32 input (layer 1)
        const float* Xf = (const float*)X;
        #pragma unroll
        for (int i = tid; i < 128 * 32; i += 256) {
            int r = i >> 5, c = (i & 31) * 4;
            float4 v = make_float4(0.f, 0.f, 0.f, 0.f);
            if (row_base + r < N) v = *(const float4*)(Xf + (size_t)(row_base + r) * 128 + c);
            __half2 h0 = __floats2half2_rn(v.x, v.y);
            __half2 h1 = __floats2half2_rn(v.z, v.w);
            uint2 u; u.x = *(uint32_t*)&h0; u.y = *(uint32_t*)&h1;
            *(uint2*)(As + r * AP + c) = u;
        }
    } else {                                   // fp16 input (layers 2-3)
        const __half* Xh = (const __half*)X;
        #pragma unroll
        for (int i = tid; i < 128 * 16; i += 256) {
            int r = i >> 4, c = (i & 15) * 8;
            uint4 v = make_uint4(0u, 0u, 0u, 0u);
            if (row_base + r < N) v = *(const uint4*)(Xh + (size_t)(row_base + r) * 128 + c);
            *(uint4*)(As + r * AP + c) = v;
        }
    }
    // ---- stage B: vector copy of pre-transposed Wt (conflict-free) ----
    #pragma unroll
    for (int i = tid; i < DOUT * 16; i += 256) {
        int n = i >> 4, kc = (i & 15) * 8;
        uint4 v = *(const uint4*)(Wt + n * 128 + kc);
        *(uint4*)(Bst + n * AP + kc) = v;
    }
    __syncthreads();

    constexpr int NT = DOUT / 8;
    float acc[NT][4];
    #pragma unroll
    for (int nt = 0; nt < NT; nt++)
        #pragma unroll
        for (int j = 0; j < 4; j++) acc[nt][j] = 0.f;

    const int g = lane >> 2;       // 0..7
    const int q = lane & 3;        // 0..3

    const uint32_t a_base = smem_u32(As) +
        (uint32_t)(((w * 16 + (lane & 15)) * AP + (lane >> 4) * 8) * 2);
    const uint32_t b_base = smem_u32(Bst) +
        (uint32_t)(((((lane & 7) + ((lane >> 4) * 8)) * AP) + ((lane >> 3) & 1) * 8) * 2);

    #pragma unroll
    for (int k0 = 0; k0 < 128; k0 += 16) {
        uint32_t a0, a1, a2, a3;
        ldsm_x4(a0, a1, a2, a3, a_base + k0 * 2);
        #pragma unroll
        for (int nt2 = 0; nt2 < NT / 2; nt2++) {
            uint32_t b0, b1, b2, b3;
            ldsm_x4(b0, b1, b2, b3, b_base + (uint32_t)((nt2 * 16 * AP + k0) * 2));
            mma_f16(acc[2 * nt2],     a0, a1, a2, a3, b0, b1);
            mma_f16(acc[2 * nt2 + 1], a0, a1, a2, a3, b2, b3);
        }
    }

    const int r0 = row_base + w * 16 + g;
    const int r1 = r0 + 8;

    float s1r0 = 0.f, s2r0 = 0.f, s1r1 = 0.f, s2r1 = 0.f;
    #pragma unroll
    for (int nt = 0; nt < NT; nt++) {
        int col = nt * 8 + 2 * q;
        float as0 = __ldg(&avs[col]), as1 = __ldg(&avs[col + 1]);
        float ad0 = __ldg(&avd[col]), ad1 = __ldg(&avd[col + 1]);
        s1r0 += acc[nt][0] * as0 + acc[nt][1] * as1;
        s2r0 += acc[nt][0] * ad0 + acc[nt][1] * ad1;
        s1r1 += acc[nt][2] * as0 + acc[nt][3] * as1;
        s2r1 += acc[nt][2] * ad0 + acc[nt][3] * ad1;
        if (r0 < N) *(__half2*)(H + (size_t)r0 * DOUT + col) =
            __floats2half2_rn(acc[nt][0], acc[nt][1]);
        if (r1 < N) *(__half2*)(H + (size_t)r1 * DOUT + col) =
            __floats2half2_rn(acc[nt][2], acc[nt][3]);
    }
    #pragma unroll
    for (int o = 1; o < 4; o <<= 1) {
        s1r0 += __shfl_xor_sync(0xffffffffu, s1r0, o);
        s2r0 += __shfl_xor_sync(0xffffffffu, s2r0, o);
        s1r1 += __shfl_xor_sync(0xffffffffu, s1r1, o);
        s2r1 += __shfl_xor_sync(0xffffffffu, s2r1, o);
    }
    if (q == 0) {
        if (r0 < N) { s_src[r0] = s1r0; s_dst[r0] = s2r0; }
        if (r1 < N) { s_src[r1] = s1r1; s_dst[r1] = s2r1; }
    }
}

// ---------------------------------------------------------------------------
// CSR build (per-dst): histogram, scan1, fused scan2+3, fill
// ---------------------------------------------------------------------------
__global__ void hist_kernel(const int* __restrict__ ei, int E, int N,
                            int* __restrict__ cnt) {
    int e = blockIdx.x * blockDim.x + threadIdx.x;
    int total = E + N;
    if (e >= total) return;
    int d = (e < E) ? ei[E + e] : (e - E);
    atomicAdd(&cnt[d], 1);
}

__global__ void scan1_kernel(const int* __restrict__ cnt, int N,
                             int* __restrict__ tmp, int* __restrict__ bsum) {
    __shared__ int sh[1024];
    int i = blockIdx.x * 1024 + threadIdx.x;
    int v = (i < N) ? cnt[i] : 0;
    sh[threadIdx.x] = v;
    __syncthreads();
    #pragma unroll
    for (int off = 1; off < 1024; off <<= 1) {
        int t = (threadIdx.x >= off) ? sh[threadIdx.x - off] : 0;
        __syncthreads();
        sh[threadIdx.x] += t;
        __syncthreads();
    }
    if (i < N) tmp[i] = sh[threadIdx.x];
    if (threadIdx.x == 1023) bsum[blockIdx.x] = sh[1023];
}

__global__ void scan23_kernel(const int* __restrict__ tmp,
                              const int* __restrict__ bsum,
                              const int* __restrict__ cnt,
                              int* __restrict__ rowptr,
                              int* __restrict__ cursor, int N, int nb) {
    __shared__ int sh[256];
    __shared__ int ex[256];
    int t = threadIdx.x;
    int v = (t < nb) ? bsum[t] : 0;
    sh[t] = v;
    __syncthreads();
    #pragma unroll
    for (int off = 1; off < 256; off <<= 1) {
        int u = (t >= off) ? sh[t - off] : 0;
        __syncthreads();
        sh[t] += u;
        __syncthreads();
    }
    ex[t] = sh[t] - v;   // exclusive block offsets
    __syncthreads();

    int i = blockIdx.x * blockDim.x + t;
    if (i < N) {
        int incl = tmp[i] + ex[i >> 10];
        rowptr[i + 1] = incl;
        cursor[i] = incl - cnt[i];
        if (i == 0) rowptr[0] = 0;
    }
}

__global__ void fill_kernel(const int* __restrict__ ei, int E, int N,
                            int* __restrict__ cursor, int* __restrict__ csrc) {
    int e = blockIdx.x * blockDim.x + threadIdx.x;
    int total = E + N;
    if (e >= total) return;
    int s, d;
    if (e < E) { s = ei[e]; d = ei[E + e]; } else { s = d = e - E; }
    int pos = atomicAdd(&cursor[d], 1);
    csrc[pos] = s;
}

// ---------------------------------------------------------------------------
// fused per-node aggregation — EXACT round-8 version (verified 303.2 µs)
// ---------------------------------------------------------------------------
#define ECACHE 8

template<int DOUT>
__global__ __launch_bounds__(256)
void aggregate_kernel(const int* __restrict__ rowptr,
                      const int* __restrict__ csrc,
                      const float* __restrict__ s_src,
                      const float* __restrict__ s_dst,
                      const __half* __restrict__ H,
                      const float* __restrict__ bias,
                      __half* __restrict__ out, int N)
{
    const int warp = (blockIdx.x * blockDim.x + threadIdx.x) >> 5;
    const int lane = threadIdx.x & 31;
    if (warp >= N) return;
    const int d   = warp;
    const int beg = rowptr[d];
    const int end = rowptr[d + 1];
    const int deg = end - beg;
    const float sd = s_dst[d];

    int   ss[ECACHE];
    float aa[ECACHE];

    // single score pass: load, leaky-relu, exp, cache, accumulate denom
    float den = 0.f;
    int cnt = 0;
    for (int i = beg + lane; i < end; i += 32) {
        int s = __ldg(&csrc[i]);
        float v = __ldg(&s_src[s]) + sd;
        v = (v > 0.f) ? v : 0.2f * v;
        float a = __expf(v);
        if (cnt < ECACHE) { ss[cnt] = s; aa[cnt] = a; }
        cnt++;
        den += a;
    }
    #pragma unroll
    for (int o = 16; o > 0; o >>= 1)
        den += __shfl_xor_sync(0xffffffffu, den, o);

    // gather pass: EPAR edges in parallel, uint4 (8 halves) per lane
    constexpr int EPAR = (DOUT == 128) ? 2 : 4;    // edges per warp step
    constexpr int LPE  = 32 / EPAR;                // lanes per edge
    const int eoff = lane / LPE;                   // which edge in group
    const int fl   = lane % LPE;                   // feature chunk (8 halves)

    const int rounds = (deg + 31) >> 5;
    float4 acc0 = make_float4(0.f, 0.f, 0.f, 0.f);
    float4 acc1 = make_float4(0.f, 0.f, 0.f, 0.f);

    for (int j0 = 0; j0 < rounds; j0++) {
        int sv; float av;
        if (j0 < ECACHE) { sv = ss[j0]; av = aa[j0]; }
        else {
            int i = beg + j0 * 32 + lane;
            sv = 0; av = 0.f;
            if (i < end) {
                sv = __ldg(&csrc[i]);
                float v = __ldg(&s_src[sv]) + sd;
                v = (v > 0.f) ? v : 0.2f * v;
                av = __expf(v);
            }
        }
        const int tmax = min(32, deg - j0 * 32);
        #pragma unroll 2
        for (int t = 0; t < tmax; t += EPAR) {
            int idx = t + eoff;
            int   s = __shfl_sync(0xffffffffu, sv, idx & 31);
            float a = __shfl_sync(0xffffffffu, av, idx & 31);
            if (idx < tmax) {
                uint4 u = *(const uint4*)(H + (size_t)s * DOUT + fl * 8);
                float2 f0 = __half22float2(*(__half2*)&u.x);
                float2 f1 = __half22float2(*(__half2*)&u.y);
                float2 f2 = __half22float2(*(__half2*)&u.z);
                float2 f3 = __half22float2(*(__half2*)&u.w);
                acc0.x += f0.x * a; acc0.y += f0.y * a;
                acc0.z += f1.x * a; acc0.w += f1.y * a;
                acc1.x += f2.x * a; acc1.y += f2.y * a;
                acc1.z += f3.x * a; acc1.w += f3.y * a;
            }
        }
    }

    // combine partial sums across edge groups
    #pragma unroll
    for (int o = LPE; o < 32; o <<= 1) {
        acc0.x += __shfl_xor_sync(0xffffffffu, acc0.x, o);
        acc0.y += __shfl_xor_sync(0xffffffffu, acc0.y, o);
        acc0.z += __shfl_xor_sync(0xffffffffu, acc0.z, o);
        acc0.w += __shfl_xor_sync(0xffffffffu, acc0.w, o);
        acc1.x += __shfl_xor_sync(0xffffffffu, acc1.x, o);
        acc1.y += __shfl_xor_sync(0xffffffffu, acc1.y, o);
        acc1.z += __shfl_xor_sync(0xffffffffu, acc1.z, o);
        acc1.w += __shfl_xor_sync(0xffffffffu, acc1.w, o);
    }
    if (eoff == 0) {
        float inv = 1.0f / den;
        float4 b0 = *(const float4*)(bias + fl * 8);
        float4 b1 = *(const float4*)(bias + fl * 8 + 4);
        float r0 = acc0.x * inv + b0.x, r1 = acc0.y * inv + b0.y;
        float r2 = acc0.z * inv + b0.z, r3 = acc0.w * inv + b0.w;
        float r4 = acc1.x * inv + b1.x, r5 = acc1.y * inv + b1.y;
        float r6 = acc1.z * inv + b1.z, r7 = acc1.w * inv + b1.w;
        __half2 p0 = __floats2half2_rn(r0, r1);
        __half2 p1 = __floats2half2_rn(r2, r3);
        __half2 p2 = __floats2half2_rn(r4, r5);
        __half2 p3 = __floats2half2_rn(r6, r7);
        uint4 u; u.x = *(uint32_t*)&p0; u.y = *(uint32_t*)&p1;
                u.z = *(uint32_t*)&p2; u.w = *(uint32_t*)&p3;
        *(uint4*)(out + (size_t)d * DOUT + fl * 8) = u;
    }
}

// ---------------------------------------------------------------------------
// two-stage mean over nodes of final [N, 64] fp16 features
// ---------------------------------------------------------------------------
__global__ void mean_part_kernel(const __half* __restrict__ H,
                                 float* __restrict__ part, int N)
{
    int col   = threadIdx.x & 63;
    int rbase = blockIdx.x * 4 + (threadIdx.x >> 6);
    float acc = 0.f;
    for (int r = rbase; r < N; r += gridDim.x * 4)
        acc += __half2float(H[(size_t)r * 64 + col]);
    __shared__ float sh[256];
    sh[threadIdx.x] = acc;
    __syncthreads();
    if (threadIdx.x < 64) {
        part[blockIdx.x * 64 + threadIdx.x] =
            sh[threadIdx.x] + sh[threadIdx.x + 64] +
            sh[threadIdx.x + 128] + sh[threadIdx.x + 192];
    }
}

__global__ void mean_final_kernel(const float* __restrict__ part,
                                  float* __restrict__ out, int nparts, int N)
{
    int col = threadIdx.x & 63;
    int seg = threadIdx.x >> 6;           // 0..3
    float acc = 0.f;
    for (int r = seg; r < nparts; r += 4)
        acc += part[r * 64 + col];
    __shared__ float sh[256];
    sh[threadIdx.x] = acc;
    __syncthreads();
    if (threadIdx.x < 64) {
        float v = sh[threadIdx.x] + sh[threadIdx.x + 64] +
                  sh[threadIdx.x + 128] + sh[threadIdx.x + 192];
        out[threadIdx.x] = v * (1.0f / (float)N);
    }
}

// ---------------------------------------------------------------------------
// host driver
// ---------------------------------------------------------------------------
extern "C" void kernel_launch(void* const* d_in, const int* in_sizes, int n_in,
                              void* d_out, int out_size)
{
    const float* x   = (const float*)d_in[0];
    const int*   ei  = (const int*)  d_in[1];
    const float* W1  = (const float*)d_in[2];
    const float* as1 = (const float*)d_in[3];
    const float* ad1 = (const float*)d_in[4];
    const float* b1  = (const float*)d_in[5];
    const float* W2  = (const float*)d_in[6];
    const float* as2 = (const float*)d_in[7];
    const float* ad2 = (const float*)d_in[8];
    const float* b2  = (const float*)d_in[9];
    const float* W3  = (const float*)d_in[10];
    const float* as3 = (const float*)d_in[11];
    const float* ad3 = (const float*)d_in[12];
    const float* b3  = (const float*)d_in[13];

    const int N = in_sizes[0] / 128;
    const int E = in_sizes[1] / 2;
    const int T = E + N;
    const int NB = ceil_div(N, 1024);

    float *pS1, *pS2, *pMp;
    __half *pH, *pXh, *pWt1, *pWt2, *pWt3;
    int *pCnt, *pTmp, *pRow, *pCur, *pBsum, *pCsrc;
    cudaGetSymbolAddress((void**)&pH,    g_h);
    cudaGetSymbolAddress((void**)&pXh,   g_xh);
    cudaGetSymbolAddress((void**)&pS1,   g_ssrc);
    cudaGetSymbolAddress((void**)&pS2,   g_sdst);
    cudaGetSymbolAddress((void**)&pWt1,  g_wt1);
    cudaGetSymbolAddress((void**)&pWt2,  g_wt2);
    cudaGetSymbolAddress((void**)&pWt3,  g_wt3);
    cudaGetSymbolAddress((void**)&pMp,   g_mpart);
    cudaGetSymbolAddress((void**)&pCnt,  g_cnt);
    cudaGetSymbolAddress((void**)&pTmp,  g_tmp);
    cudaGetSymbolAddress((void**)&pRow,  g_rowptr);
    cudaGetSymbolAddress((void**)&pCur,  g_cursor);
    cudaGetSymbolAddress((void**)&pBsum, g_bsum);
    cudaGetSymbolAddress((void**)&pCsrc, g_csrc);

    // dynamic smem for fp16 GEMMs
    const int smem128 = (128 * 136 + 128 * 136) * 2;   // 69632
    const int smem64  = (128 * 136 + 64 * 136) * 2;    // 52224
    cudaFuncSetAttribute(gemm_f16_kernel<128, float>,
                         cudaFuncAttributeMaxDynamicSharedMemorySize, smem128);
    cudaFuncSetAttribute(gemm_f16_kernel<128, __half>,
                         cudaFuncAttributeMaxDynamicSharedMemorySize, smem128);
    cudaFuncSetAttribute(gemm_f16_kernel<64, __half>,
                         cudaFuncAttributeMaxDynamicSharedMemorySize, smem64);

    // ---------------- CSR build + layer-1 GEMM interleaved ----------------
    // (gemm1 kept at launch index 3 so the fixed ncu slot profiles it)
    init_wt_kernel<<<ceil_div(N, 256), 256>>>(W1, W2, W3, pWt1, pWt2, pWt3, pCnt, N); // 0
    hist_kernel<<<ceil_div(T, 256), 256>>>(ei, E, N, pCnt);                       // 1
    scan1_kernel<<<NB, 1024>>>(pCnt, N, pTmp, pBsum);                             // 2
    gemm_f16_kernel<128, float><<<ceil_div(N, 128), 256, smem128>>>(              // 3
        x, pWt1, as1, ad1, pH, pS1, pS2, N);
    scan23_kernel<<<ceil_div(N, 256), 256>>>(pTmp, pBsum, pCnt, pRow, pCur, N, NB); // 4
    fill_kernel<<<ceil_div(T, 256), 256>>>(ei, E, N, pCur, pCsrc);                // 5

    // ---------------- layer 1 aggregate -> pXh (fp16) ----------------
    aggregate_kernel<128><<<ceil_div(N, 8), 256>>>(pRow, pCsrc, pS1, pS2, pH, b1, pXh, N);

    // ---------------- layer 2: pXh -> pXh (dout=128) ----------------
    gemm_f16_kernel<128, __half><<<ceil_div(N, 128), 256, smem128>>>(
        pXh, pWt2, as2, ad2, pH, pS1, pS2, N);
    aggregate_kernel<128><<<ceil_div(N, 8), 256>>>(pRow, pCsrc, pS1, pS2, pH, b2, pXh, N);

    // ---------------- layer 3: pXh -> pXh (dout=64, fp16 out) ----------------
    gemm_f16_kernel<64, __half><<<ceil_div(N, 128), 256, smem64>>>(
        pXh, pWt3, as3, ad3, pH, pS1, pS2, N);
    aggregate_kernel<64><<<ceil_div(N, 8), 256>>>(pRow, pCsrc, pS1, pS2, pH, b3, pXh, N);

    // ---------------- global mean -> d_out [64] ----------------
    mean_part_kernel<<<1024, 256>>>(pXh, pMp, N);
    mean_final_kernel<<<1, 256>>>(pMp, (float*)d_out, 1024, N);
}

// round 11
// speedup vs baseline: 1.0928x; 1.0434x over previous
#include <cuda_runtime.h>
#include <cuda_fp16.h>
#include <math.h>
#include <stdint.h>

#define DIN   128
#define N_MAX 100000
#define E_MAX 1600000
#define T_MAX (E_MAX + N_MAX)

// ---------------------------------------------------------------------------
// persistent scratch (no allocations allowed)
// ---------------------------------------------------------------------------
__device__ __half g_h  [(size_t)N_MAX * 128];   // gemm output h (fp16 gather path)
__device__ __half g_xh [(size_t)N_MAX * 128];   // layer output (fp16)
__device__ float  g_ssrc[N_MAX];
__device__ float  g_sdst[N_MAX];
__device__ __half g_wt1[128 * 128];
__device__ __half g_wt2[128 * 128];
__device__ __half g_wt3[64 * 128];
__device__ float  g_mpart[1024 * 64];

__device__ int g_cnt   [N_MAX];
__device__ int g_tmp   [N_MAX];
__device__ int g_rowptr[N_MAX + 1];
__device__ int g_cursor[N_MAX];
__device__ int g_bsum  [256];
__device__ int g_csrc  [T_MAX];

static inline int ceil_div(int a, int b) { return (a + b - 1) / b; }

// ---------------------------------------------------------------------------
// mma / ldmatrix helpers
// ---------------------------------------------------------------------------
__device__ __forceinline__ void mma_f16(float c[4], uint32_t a0, uint32_t a1,
                                        uint32_t a2, uint32_t a3,
                                        uint32_t b0, uint32_t b1) {
    asm volatile(
        "mma.sync.aligned.m16n8k16.row.col.f32.f16.f16.f32 "
        "{%0,%1,%2,%3}, {%4,%5,%6,%7}, {%8,%9}, {%0,%1,%2,%3};"
        : "+f"(c[0]), "+f"(c[1]), "+f"(c[2]), "+f"(c[3])
        : "r"(a0), "r"(a1), "r"(a2), "r"(a3), "r"(b0), "r"(b1));
}

__device__ __forceinline__ void ldsm_x4(uint32_t& r0, uint32_t& r1,
                                        uint32_t& r2, uint32_t& r3,
                                        uint32_t addr) {
    asm volatile("ldmatrix.sync.aligned.m8n8.x4.shared.b16 {%0,%1,%2,%3}, [%4];"
                 : "=r"(r0), "=r"(r1), "=r"(r2), "=r"(r3) : "r"(addr));
}

__device__ __forceinline__ uint32_t smem_u32(const void* p) {
    uint32_t a;
    asm("{ .reg .u64 t; cvta.to.shared.u64 t, %1; cvt.u32.u64 %0, t; }"
        : "=r"(a) : "l"(p));
    return a;
}

// ---------------------------------------------------------------------------
// fused: zero cnt[] + W transposes for all 3 layers (Wt[n][k] fp16 = W[k][n])
// ---------------------------------------------------------------------------
__global__ void init_wt_kernel(const float* __restrict__ W1,
                               const float* __restrict__ W2,
                               const float* __restrict__ W3,
                               __half* __restrict__ Wt1,
                               __half* __restrict__ Wt2,
                               __half* __restrict__ Wt3,
                               int* __restrict__ cnt, int N) {
    int i = blockIdx.x * 256 + threadIdx.x;
    if (i < N) cnt[i] = 0;
    if (i < 128 * 128) {
        int n = i >> 7, k = i & 127;
        Wt1[i] = __float2half(W1[k * 128 + n]);
    } else if (i < 2 * 128 * 128) {
        int j = i - 128 * 128;
        int n = j >> 7, k = j & 127;
        Wt2[j] = __float2half(W2[k * 128 + n]);
    } else if (i < 2 * 128 * 128 + 64 * 128) {
        int l = i - 2 * 128 * 128;
        int n = l >> 7, k = l & 127;
        Wt3[l] = __float2half(W3[k * 64 + n]);
    }
}

// ---------------------------------------------------------------------------
// GEMM (tensor core, fp16 in / fp32 acc, ldmatrix fragments) + fused scores
// (frozen since round 8 — verified win)
// ---------------------------------------------------------------------------
template<int DOUT, typename XT>
__global__ __launch_bounds__(256)
void gemm_f16_kernel(const XT* __restrict__ X, const __half* __restrict__ Wt,
                     const float* __restrict__ avs, const float* __restrict__ avd,
                     __half* __restrict__ H,
                     float* __restrict__ s_src, float* __restrict__ s_dst, int N)
{
    extern __shared__ __half hsmem[];
    constexpr int AP = 136;                    // padded row stride (halves)
    __half* As  = hsmem;                       // [128][AP]
    __half* Bst = hsmem + 128 * AP;            // [DOUT][AP]

    const int tid  = threadIdx.x;
    const int lane = tid & 31;
    const int w    = tid >> 5;
    const int row_base = blockIdx.x * 128;

    // ---- stage A (128 x 128) ----
    if (sizeof(XT) == 4) {                     // fp32 input (layer 1)
        const float* Xf = (const float*)X;
        #pragma unroll
        for (int i = tid; i < 128 * 32; i += 256) {
            int r = i >> 5, c = (i & 31) * 4;
            float4 v = make_float4(0.f, 0.f, 0.f, 0.f);
            if (row_base + r < N) v = *(const float4*)(Xf + (size_t)(row_base + r) * 128 + c);
            __half2 h0 = __floats2half2_rn(v.x, v.y);
            __half2 h1 = __floats2half2_rn(v.z, v.w);
            uint2 u; u.x = *(uint32_t*)&h0; u.y = *(uint32_t*)&h1;
            *(uint2*)(As + r * AP + c) = u;
        }
    } else {                                   // fp16 input (layers 2-3)
        const __half* Xh = (const __half*)X;
        #pragma unroll
        for (int i = tid; i < 128 * 16; i += 256) {
            int r = i >> 4, c = (i & 15) * 8;
            uint4 v = make_uint4(0u, 0u, 0u, 0u);
            if (row_base + r < N) v = *(const uint4*)(Xh + (size_t)(row_base + r) * 128 + c);
            *(uint4*)(As + r * AP + c) = v;
        }
    }
    // ---- stage B: vector copy of pre-transposed Wt (conflict-free) ----
    #pragma unroll
    for (int i = tid; i < DOUT * 16; i += 256) {
        int n = i >> 4, kc = (i & 15) * 8;
        uint4 v = *(const uint4*)(Wt + n * 128 + kc);
        *(uint4*)(Bst + n * AP + kc) = v;
    }
    __syncthreads();

    constexpr int NT = DOUT / 8;
    float acc[NT][4];
    #pragma unroll
    for (int nt = 0; nt < NT; nt++)
        #pragma unroll
        for (int j = 0; j < 4; j++) acc[nt][j] = 0.f;

    const int g = lane >> 2;       // 0..7
    const int q = lane & 3;        // 0..3

    const uint32_t a_base = smem_u32(As) +
        (uint32_t)(((w * 16 + (lane & 15)) * AP + (lane >> 4) * 8) * 2);
    const uint32_t b_base = smem_u32(Bst) +
        (uint32_t)(((((lane & 7) + ((lane >> 4) * 8)) * AP) + ((lane >> 3) & 1) * 8) * 2);

    #pragma unroll
    for (int k0 = 0; k0 < 128; k0 += 16) {
        uint32_t a0, a1, a2, a3;
        ldsm_x4(a0, a1, a2, a3, a_base + k0 * 2);
        #pragma unroll
        for (int nt2 = 0; nt2 < NT / 2; nt2++) {
            uint32_t b0, b1, b2, b3;
            ldsm_x4(b0, b1, b2, b3, b_base + (uint32_t)((nt2 * 16 * AP + k0) * 2));
            mma_f16(acc[2 * nt2],     a0, a1, a2, a3, b0, b1);
            mma_f16(acc[2 * nt2 + 1], a0, a1, a2, a3, b2, b3);
        }
    }

    const int r0 = row_base + w * 16 + g;
    const int r1 = r0 + 8;

    float s1r0 = 0.f, s2r0 = 0.f, s1r1 = 0.f, s2r1 = 0.f;
    #pragma unroll
    for (int nt = 0; nt < NT; nt++) {
        int col = nt * 8 + 2 * q;
        float as0 = __ldg(&avs[col]), as1 = __ldg(&avs[col + 1]);
        float ad0 = __ldg(&avd[col]), ad1 = __ldg(&avd[col + 1]);
        s1r0 += acc[nt][0] * as0 + acc[nt][1] * as1;
        s2r0 += acc[nt][0] * ad0 + acc[nt][1] * ad1;
        s1r1 += acc[nt][2] * as0 + acc[nt][3] * as1;
        s2r1 += acc[nt][2] * ad0 + acc[nt][3] * ad1;
        if (r0 < N) *(__half2*)(H + (size_t)r0 * DOUT + col) =
            __floats2half2_rn(acc[nt][0], acc[nt][1]);
        if (r1 < N) *(__half2*)(H + (size_t)r1 * DOUT + col) =
            __floats2half2_rn(acc[nt][2], acc[nt][3]);
    }
    #pragma unroll
    for (int o = 1; o < 4; o <<= 1) {
        s1r0 += __shfl_xor_sync(0xffffffffu, s1r0, o);
        s2r0 += __shfl_xor_sync(0xffffffffu, s2r0, o);
        s1r1 += __shfl_xor_sync(0xffffffffu, s1r1, o);
        s2r1 += __shfl_xor_sync(0xffffffffu, s2r1, o);
    }
    if (q == 0) {
        if (r0 < N) { s_src[r0] = s1r0; s_dst[r0] = s2r0; }
        if (r1 < N) { s_src[r1] = s1r1; s_dst[r1] = s2r1; }
    }
}

// ---------------------------------------------------------------------------
// CSR build (per-dst): histogram, scan1, fused scan2+3, fill
// ---------------------------------------------------------------------------
__global__ void hist_kernel(const int* __restrict__ ei, int E, int N,
                            int* __restrict__ cnt) {
    int e = blockIdx.x * blockDim.x + threadIdx.x;
    int total = E + N;
    if (e >= total) return;
    int d = (e < E) ? ei[E + e] : (e - E);
    atomicAdd(&cnt[d], 1);
}

__global__ void scan1_kernel(const int* __restrict__ cnt, int N,
                             int* __restrict__ tmp, int* __restrict__ bsum) {
    __shared__ int sh[1024];
    int i = blockIdx.x * 1024 + threadIdx.x;
    int v = (i < N) ? cnt[i] : 0;
    sh[threadIdx.x] = v;
    __syncthreads();
    #pragma unroll
    for (int off = 1; off < 1024; off <<= 1) {
        int t = (threadIdx.x >= off) ? sh[threadIdx.x - off] : 0;
        __syncthreads();
        sh[threadIdx.x] += t;
        __syncthreads();
    }
    if (i < N) tmp[i] = sh[threadIdx.x];
    if (threadIdx.x == 1023) bsum[blockIdx.x] = sh[1023];
}

__global__ void scan23_kernel(const int* __restrict__ tmp,
                              const int* __restrict__ bsum,
                              const int* __restrict__ cnt,
                              int* __restrict__ rowptr,
                              int* __restrict__ cursor, int N, int nb) {
    __shared__ int sh[256];
    __shared__ int ex[256];
    int t = threadIdx.x;
    int v = (t < nb) ? bsum[t] : 0;
    sh[t] = v;
    __syncthreads();
    #pragma unroll
    for (int off = 1; off < 256; off <<= 1) {
        int u = (t >= off) ? sh[t - off] : 0;
        __syncthreads();
        sh[t] += u;
        __syncthreads();
    }
    ex[t] = sh[t] - v;   // exclusive block offsets
    __syncthreads();

    int i = blockIdx.x * blockDim.x + t;
    if (i < N) {
        int incl = tmp[i] + ex[i >> 10];
        rowptr[i + 1] = incl;
        cursor[i] = incl - cnt[i];
        if (i == 0) rowptr[0] = 0;
    }
}

__global__ void fill_kernel(const int* __restrict__ ei, int E, int N,
                            int* __restrict__ cursor, int* __restrict__ csrc) {
    int e = blockIdx.x * blockDim.x + threadIdx.x;
    int total = E + N;
    if (e >= total) return;
    int s, d;
    if (e < E) { s = ei[e]; d = ei[E + e]; } else { s = d = e - E; }
    int pos = atomicAdd(&cursor[d], 1);
    csrc[pos] = s;
}

// ---------------------------------------------------------------------------
// fused per-node aggregation — round-8 body, 64-thread blocks (2 warps/CTA)
// to cut CTA-granularity degree-skew residency waste
// ---------------------------------------------------------------------------
#define ECACHE 8

template<int DOUT>
__global__ __launch_bounds__(64)
void aggregate_kernel(const int* __restrict__ rowptr,
                      const int* __restrict__ csrc,
                      const float* __restrict__ s_src,
                      const float* __restrict__ s_dst,
                      const __half* __restrict__ H,
                      const float* __restrict__ bias,
                      __half* __restrict__ out, int N)
{
    const int warp = (blockIdx.x * blockDim.x + threadIdx.x) >> 5;
    const int lane = threadIdx.x & 31;
    if (warp >= N) return;
    const int d   = warp;
    const int beg = rowptr[d];
    const int end = rowptr[d + 1];
    const int deg = end - beg;
    const float sd = s_dst[d];

    int   ss[ECACHE];
    float aa[ECACHE];

    // single score pass: load, leaky-relu, exp, cache, accumulate denom
    float den = 0.f;
    int cnt = 0;
    for (int i = beg + lane; i < end; i += 32) {
        int s = __ldg(&csrc[i]);
        float v = __ldg(&s_src[s]) + sd;
        v = (v > 0.f) ? v : 0.2f * v;
        float a = __expf(v);
        if (cnt < ECACHE) { ss[cnt] = s; aa[cnt] = a; }
        cnt++;
        den += a;
    }
    #pragma unroll
    for (int o = 16; o > 0; o >>= 1)
        den += __shfl_xor_sync(0xffffffffu, den, o);

    // gather pass: EPAR edges in parallel, uint4 (8 halves) per lane
    constexpr int EPAR = (DOUT == 128) ? 2 : 4;    // edges per warp step
    constexpr int LPE  = 32 / EPAR;                // lanes per edge
    const int eoff = lane / LPE;                   // which edge in group
    const int fl   = lane % LPE;                   // feature chunk (8 halves)

    const int rounds = (deg + 31) >> 5;
    float4 acc0 = make_float4(0.f, 0.f, 0.f, 0.f);
    float4 acc1 = make_float4(0.f, 0.f, 0.f, 0.f);

    for (int j0 = 0; j0 < rounds; j0++) {
        int sv; float av;
        if (j0 < ECACHE) { sv = ss[j0]; av = aa[j0]; }
        else {
            int i = beg + j0 * 32 + lane;
            sv = 0; av = 0.f;
            if (i < end) {
                sv = __ldg(&csrc[i]);
                float v = __ldg(&s_src[sv]) + sd;
                v = (v > 0.f) ? v : 0.2f * v;
                av = __expf(v);
            }
        }
        const int tmax = min(32, deg - j0 * 32);
        #pragma unroll 2
        for (int t = 0; t < tmax; t += EPAR) {
            int idx = t + eoff;
            int   s = __shfl_sync(0xffffffffu, sv, idx & 31);
            float a = __shfl_sync(0xffffffffu, av, idx & 31);
            if (idx < tmax) {
                uint4 u = *(const uint4*)(H + (size_t)s * DOUT + fl * 8);
                float2 f0 = __half22float2(*(__half2*)&u.x);
                float2 f1 = __half22float2(*(__half2*)&u.y);
                float2 f2 = __half22float2(*(__half2*)&u.z);
                float2 f3 = __half22float2(*(__half2*)&u.w);
                acc0.x += f0.x * a; acc0.y += f0.y * a;
                acc0.z += f1.x * a; acc0.w += f1.y * a;
                acc1.x += f2.x * a; acc1.y += f2.y * a;
                acc1.z += f3.x * a; acc1.w += f3.y * a;
            }
        }
    }

    // combine partial sums across edge groups
    #pragma unroll
    for (int o = LPE; o < 32; o <<= 1) {
        acc0.x += __shfl_xor_sync(0xffffffffu, acc0.x, o);
        acc0.y += __shfl_xor_sync(0xffffffffu, acc0.y, o);
        acc0.z += __shfl_xor_sync(0xffffffffu, acc0.z, o);
        acc0.w += __shfl_xor_sync(0xffffffffu, acc0.w, o);
        acc1.x += __shfl_xor_sync(0xffffffffu, acc1.x, o);
        acc1.y += __shfl_xor_sync(0xffffffffu, acc1.y, o);
        acc1.z += __shfl_xor_sync(0xffffffffu, acc1.z, o);
        acc1.w += __shfl_xor_sync(0xffffffffu, acc1.w, o);
    }
    if (eoff == 0) {
        float inv = 1.0f / den;
        float4 b0 = *(const float4*)(bias + fl * 8);
        float4 b1 = *(const float4*)(bias + fl * 8 + 4);
        float r0 = acc0.x * inv + b0.x, r1 = acc0.y * inv + b0.y;
        float r2 = acc0.z * inv + b0.z, r3 = acc0.w * inv + b0.w;
        float r4 = acc1.x * inv + b1.x, r5 = acc1.y * inv + b1.y;
        float r6 = acc1.z * inv + b1.z, r7 = acc1.w * inv + b1.w;
        __half2 p0 = __floats2half2_rn(r0, r1);
        __half2 p1 = __floats2half2_rn(r2, r3);
        __half2 p2 = __floats2half2_rn(r4, r5);
        __half2 p3 = __floats2half2_rn(r6, r7);
        uint4 u; u.x = *(uint32_t*)&p0; u.y = *(uint32_t*)&p1;
                u.z = *(uint32_t*)&p2; u.w = *(uint32_t*)&p3;
        *(uint4*)(out + (size_t)d * DOUT + fl * 8) = u;
    }
}

// ---------------------------------------------------------------------------
// two-stage mean over nodes of final [N, 64] fp16 features
// ---------------------------------------------------------------------------
__global__ void mean_part_kernel(const __half* __restrict__ H,
                                 float* __restrict__ part, int N)
{
    int col   = threadIdx.x & 63;
    int rbase = blockIdx.x * 4 + (threadIdx.x >> 6);
    float acc = 0.f;
    for (int r = rbase; r < N; r += gridDim.x * 4)
        acc += __half2float(H[(size_t)r * 64 + col]);
    __shared__ float sh[256];
    sh[threadIdx.x] = acc;
    __syncthreads();
    if (threadIdx.x < 64) {
        part[blockIdx.x * 64 + threadIdx.x] =
            sh[threadIdx.x] + sh[threadIdx.x + 64] +
            sh[threadIdx.x + 128] + sh[threadIdx.x + 192];
    }
}

__global__ void mean_final_kernel(const float* __restrict__ part,
                                  float* __restrict__ out, int nparts, int N)
{
    int col = threadIdx.x & 63;
    int seg = threadIdx.x >> 6;           // 0..3
    float acc = 0.f;
    for (int r = seg; r < nparts; r += 4)
        acc += part[r * 64 + col];
    __shared__ float sh[256];
    sh[threadIdx.x] = acc;
    __syncthreads();
    if (threadIdx.x < 64) {
        float v = sh[threadIdx.x] + sh[threadIdx.x + 64] +
                  sh[threadIdx.x + 128] + sh[threadIdx.x + 192];
        out[threadIdx.x] = v * (1.0f / (float)N);
    }
}

// ---------------------------------------------------------------------------
// host driver
// ---------------------------------------------------------------------------
extern "C" void kernel_launch(void* const* d_in, const int* in_sizes, int n_in,
                              void* d_out, int out_size)
{
    const float* x   = (const float*)d_in[0];
    const int*   ei  = (const int*)  d_in[1];
    const float* W1  = (const float*)d_in[2];
    const float* as1 = (const float*)d_in[3];
    const float* ad1 = (const float*)d_in[4];
    const float* b1  = (const float*)d_in[5];
    const float* W2  = (const float*)d_in[6];
    const float* as2 = (const float*)d_in[7];
    const float* ad2 = (const float*)d_in[8];
    const float* b2  = (const float*)d_in[9];
    const float* W3  = (const float*)d_in[10];
    const float* as3 = (const float*)d_in[11];
    const float* ad3 = (const float*)d_in[12];
    const float* b3  = (const float*)d_in[13];

    const int N = in_sizes[0] / 128;
    const int E = in_sizes[1] / 2;
    const int T = E + N;
    const int NB = ceil_div(N, 1024);

    float *pS1, *pS2, *pMp;
    __half *pH, *pXh, *pWt1, *pWt2, *pWt3;
    int *pCnt, *pTmp, *pRow, *pCur, *pBsum, *pCsrc;
    cudaGetSymbolAddress((void**)&pH,    g_h);
    cudaGetSymbolAddress((void**)&pXh,   g_xh);
    cudaGetSymbolAddress((void**)&pS1,   g_ssrc);
    cudaGetSymbolAddress((void**)&pS2,   g_sdst);
    cudaGetSymbolAddress((void**)&pWt1,  g_wt1);
    cudaGetSymbolAddress((void**)&pWt2,  g_wt2);
    cudaGetSymbolAddress((void**)&pWt3,  g_wt3);
    cudaGetSymbolAddress((void**)&pMp,   g_mpart);
    cudaGetSymbolAddress((void**)&pCnt,  g_cnt);
    cudaGetSymbolAddress((void**)&pTmp,  g_tmp);
    cudaGetSymbolAddress((void**)&pRow,  g_rowptr);
    cudaGetSymbolAddress((void**)&pCur,  g_cursor);
    cudaGetSymbolAddress((void**)&pBsum, g_bsum);
    cudaGetSymbolAddress((void**)&pCsrc, g_csrc);

    // dynamic smem for fp16 GEMMs
    const int smem128 = (128 * 136 + 128 * 136) * 2;   // 69632
    const int smem64  = (128 * 136 + 64 * 136) * 2;    // 52224
    cudaFuncSetAttribute(gemm_f16_kernel<128, float>,
                         cudaFuncAttributeMaxDynamicSharedMemorySize, smem128);
    cudaFuncSetAttribute(gemm_f16_kernel<128, __half>,
                         cudaFuncAttributeMaxDynamicSharedMemorySize, smem128);
    cudaFuncSetAttribute(gemm_f16_kernel<64, __half>,
                         cudaFuncAttributeMaxDynamicSharedMemorySize, smem64);

    // ---------------- CSR build + layer-1 GEMM interleaved ----------------
    // (gemm1 kept at launch index 3 so the fixed ncu slot profiles it)
    init_wt_kernel<<<ceil_div(N, 256), 256>>>(W1, W2, W3, pWt1, pWt2, pWt3, pCnt, N); // 0
    hist_kernel<<<ceil_div(T, 256), 256>>>(ei, E, N, pCnt);                       // 1
    scan1_kernel<<<NB, 1024>>>(pCnt, N, pTmp, pBsum);                             // 2
    gemm_f16_kernel<128, float><<<ceil_div(N, 128), 256, smem128>>>(              // 3
        x, pWt1, as1, ad1, pH, pS1, pS2, N);
    scan23_kernel<<<ceil_div(N, 256), 256>>>(pTmp, pBsum, pCnt, pRow, pCur, N, NB); // 4
    fill_kernel<<<ceil_div(T, 256), 256>>>(ei, E, N, pCur, pCsrc);                // 5

    // ---------------- layer 1 aggregate -> pXh (fp16) ----------------
    aggregate_kernel<128><<<ceil_div(N, 2), 64>>>(pRow, pCsrc, pS1, pS2, pH, b1, pXh, N);

    // ---------------- layer 2: pXh -> pXh (dout=128) ----------------
    gemm_f16_kernel<128, __half><<<ceil_div(N, 128), 256, smem128>>>(
        pXh, pWt2, as2, ad2, pH, pS1, pS2, N);
    aggregate_kernel<128><<<ceil_div(N, 2), 64>>>(pRow, pCsrc, pS1, pS2, pH, b2, pXh, N);

    // ---------------- layer 3: pXh -> pXh (dout=64, fp16 out) ----------------
    gemm_f16_kernel<64, __half><<<ceil_div(N, 128), 256, smem64>>>(
        pXh, pWt3, as3, ad3, pH, pS1, pS2, N);
    aggregate_kernel<64><<<ceil_div(N, 2), 64>>>(pRow, pCsrc, pS1, pS2, pH, b3, pXh, N);

    // ---------------- global mean -> d_out [64] ----------------
    mean_part_kernel<<<1024, 256>>>(pXh, pMp, N);
    mean_final_kernel<<<1, 256>>>(pMp, (float*)d_out, 1024, N);
}